// round 15
// baseline (speedup 1.0000x reference)
#include <cuda_runtime.h>
#include <cuda_fp16.h>
#include <math.h>

#define BATCH 4
#define SEQ   2048
#define DIM   1024
#define HEADS 16
#define DH    64
#define INNER 1024
#define MTOT  (BATCH*SEQ)   // 8192
#define QKVN  (3*INNER)     // 3072
#define BH    (BATCH*HEADS) // 64

typedef unsigned int uint32;

// ---------------- fp16 (half2-packed) scratch -------------------------------
__device__ uint32 g_xp  [MTOT][DIM/2];
__device__ uint32 g_wqkv[QKVN][DIM/2];
__device__ uint32 g_wout[DIM][INNER/2];
__device__ uint32 g_q [BH][SEQ][DH/2];    // pre-scaled by exp(temperature)*log2(e)
__device__ uint32 g_k [BH][SEQ][DH/2];
__device__ uint32 g_v [BH][SEQ][DH/2];
__device__ uint32 g_vT[BH][DH][SEQ/2];
__device__ uint32 g_ao[MTOT][INNER/2];

// ---------------- helpers ---------------------------------------------------
__device__ __forceinline__ uint32 cvt_h2(float x, float y) {
    __half2 h = __floats2half2_rn(x, y);
    return *reinterpret_cast<uint32*>(&h);
}

__device__ __forceinline__ uint32 h2ex2(uint32 x) {
    uint32 r;
    asm volatile("ex2.approx.f16x2 %0, %1;\n" : "=r"(r) : "r"(x));
    return r;
}

__device__ __forceinline__ void mma_f16(float* c, uint32 a0, uint32 a1, uint32 a2,
                                        uint32 a3, uint32 b0, uint32 b1) {
    asm volatile(
        "mma.sync.aligned.m16n8k16.row.col.f32.f16.f16.f32 "
        "{%0,%1,%2,%3},{%4,%5,%6,%7},{%8,%9},{%0,%1,%2,%3};\n"
        : "+f"(c[0]), "+f"(c[1]), "+f"(c[2]), "+f"(c[3])
        : "r"(a0), "r"(a1), "r"(a2), "r"(a3), "r"(b0), "r"(b1));
}

__device__ __forceinline__ uint32 smem_u32(const void* p) {
    uint32 a;
    asm("{ .reg .u64 t; cvta.to.shared.u64 t, %1; cvt.u32.u64 %0, t; }"
        : "=r"(a) : "l"(p));
    return a;
}

__device__ __forceinline__ uint32 swz(uint32 o) { return o ^ ((o >> 3) & 0x70); }

__device__ __forceinline__ void cpa16(uint32 dst, const void* src) {
    asm volatile("cp.async.cg.shared.global [%0], [%1], 16;\n" :: "r"(dst), "l"(src));
}
__device__ __forceinline__ void cp_commit() { asm volatile("cp.async.commit_group;\n"); }
template<int N> __device__ __forceinline__ void cp_wait() {
    asm volatile("cp.async.wait_group %0;\n" :: "n"(N));
}

__device__ __forceinline__ void ldm4(uint32& r0, uint32& r1, uint32& r2, uint32& r3,
                                     uint32 addr) {
    asm volatile("ldmatrix.sync.aligned.m8n8.x4.shared.b16 {%0,%1,%2,%3},[%4];\n"
        : "=r"(r0), "=r"(r1), "=r"(r2), "=r"(r3) : "r"(addr));
}

// ---------------- prep kernels ----------------------------------------------
__global__ __launch_bounds__(256) void pack_x_kernel(const float* __restrict__ x) {
    int i = blockIdx.x * 256 + threadIdx.x;
    float2 v = ((const float2*)x)[i];
    (&g_xp[0][0])[i] = cvt_h2(v.x, v.y);
}

__global__ __launch_bounds__(256) void pack_wT_kernel(const float* __restrict__ w, int mode) {
    __shared__ float sm[64][65];
    const int K = mode ? INNER : DIM;
    const int N = mode ? DIM : QKVN;
    uint32* __restrict__ dst = mode ? &g_wout[0][0] : &g_wqkv[0][0];
    const int k0 = blockIdx.x * 64, n0 = blockIdx.y * 64;
    const int t = threadIdx.x;
#pragma unroll
    for (int it = 0; it < 4; it++) {
        int idx = t + it * 256;
        int r = idx >> 4, c = (idx & 15) * 4;
        float4 f = *(const float4*)&w[(size_t)(k0 + r) * N + n0 + c];
        sm[r][c] = f.x; sm[r][c+1] = f.y; sm[r][c+2] = f.z; sm[r][c+3] = f.w;
    }
    __syncthreads();
#pragma unroll
    for (int it = 0; it < 8; it++) {
        int idx = t + it * 256;
        int n = idx >> 5, kp = idx & 31;
        dst[(size_t)(n0 + n) * (K/2) + (k0 >> 1) + kp] = cvt_h2(sm[2*kp][n], sm[2*kp+1][n]);
    }
}

__global__ __launch_bounds__(256) void vT_kernel() {
    __shared__ uint32 sm[64][36];
    const int n0 = blockIdx.x * 64, bhi = blockIdx.y;
    const int t = threadIdx.x;
#pragma unroll
    for (int it = 0; it < 2; it++) {
        int idx = t + it * 256;
        int r = idx >> 3, c = (idx & 7) * 4;
        *(uint4*)&sm[r][c] = *(const uint4*)&g_v[bhi][n0 + r][c];
    }
    __syncthreads();
#pragma unroll
    for (int it = 0; it < 8; it++) {
        int idx = t + it * 256;              // 64*32 = 2048
        int d = idx >> 5, npl = idx & 31;
        uint32 w0 = sm[2*npl][d >> 1];
        uint32 w1 = sm[2*npl + 1][d >> 1];
        uint32 o = (d & 1) ? __byte_perm(w0, w1, 0x7632) : __byte_perm(w0, w1, 0x5410);
        g_vT[bhi][d][(n0 >> 1) + npl] = o;
    }
}

// ---------------- pipelined GEMM (128x128 tile, BK=32, fp16, 3-stage) -------
__device__ __forceinline__ void gemm_stage(uint32 sbase, int stage,
    const uint32* __restrict__ A, const uint32* __restrict__ B, int k2, int kc)
{
    const int t = threadIdx.x;
#pragma unroll
    for (int i = 0; i < 4; i++) {
        int cid = t + i * 256;          // 0..1023
        int tile = cid >> 9;            // 0=A 1=B
        int w = cid & 511;
        int r = w >> 2, c = w & 3;
        const uint32* src = (tile ? B : A) + (size_t)r * k2 + kc * 16 + c * 4;
        cpa16(sbase + stage * 16384 + tile * 8192 + swz((uint32)(r * 64 + c * 16)), src);
    }
}

__device__ __forceinline__ void gemm_compute(uint32 sbase, int stage,
                                             float (&acc)[2][8][4])
{
    const int lane = threadIdx.x & 31, warp = threadIdx.x >> 5;
    const int wm = warp & 3, wn = warp >> 2;
    const uint32 pb = sbase + stage * 16384;

    const int ra = wm * 32 + (lane & 15);
    const int ca = (lane >> 4) * 16;
    const int rbl = (lane & 7) + ((lane >> 4) ? 8 : 0);
    const int cbl = ((lane >> 3) & 1) * 16;

#pragma unroll
    for (int s = 0; s < 2; s++) {
        uint32 a[2][4];
#pragma unroll
        for (int mt = 0; mt < 2; mt++)
            ldm4(a[mt][0], a[mt][1], a[mt][2], a[mt][3],
                 pb + swz((uint32)((ra + mt * 16) * 64 + s * 32 + ca)));
        uint32 bf[4][4];
#pragma unroll
        for (int p = 0; p < 4; p++)
            ldm4(bf[p][0], bf[p][1], bf[p][2], bf[p][3],
                 pb + 8192 + swz((uint32)((wn * 64 + p * 16 + rbl) * 64 + s * 32 + cbl)));
#pragma unroll
        for (int mt = 0; mt < 2; mt++)
#pragma unroll
            for (int nt = 0; nt < 8; nt++)
                mma_f16(acc[mt][nt], a[mt][0], a[mt][1], a[mt][2], a[mt][3],
                        bf[nt >> 1][(nt & 1) * 2], bf[nt >> 1][(nt & 1) * 2 + 1]);
    }
}

// ---------------- kernel 1: QKV projection ----------------------------------
__global__ __launch_bounds__(256, 2) void qkv_gemm_kernel(const float* __restrict__ temp) {
    __shared__ __align__(128) uint32 smp[3][4096];   // 48KB
    const uint32 sbase = smem_u32(smp);
    const int row0 = blockIdx.x * 128, col0 = blockIdx.y * 128;
    const uint32 *A = &g_xp[row0][0], *B = &g_wqkv[col0][0];
    const int iters = DIM / 32;

    float acc[2][8][4];
#pragma unroll
    for (int i = 0; i < 2; i++)
#pragma unroll
        for (int j = 0; j < 8; j++)
#pragma unroll
            for (int e = 0; e < 4; e++) acc[i][j][e] = 0.f;

    gemm_stage(sbase, 0, A, B, DIM/2, 0); cp_commit();
    gemm_stage(sbase, 1, A, B, DIM/2, 1); cp_commit();

    for (int it = 0; it < iters; it++) {
        cp_wait<1>(); __syncthreads();
        gemm_compute(sbase, it % 3, acc);
        if (it + 2 < iters)
            gemm_stage(sbase, (it + 2) % 3, A, B, DIM/2, it + 2);
        cp_commit();
    }

    const int lane = threadIdx.x & 31, warp = threadIdx.x >> 5;
    const int wm = warp & 3, wn = warp >> 2;
    const int g = lane >> 2, tig = lane & 3;
    // q pre-scale folds softmax scale AND log2(e) so attention uses ex2 directly
    const float scale = __expf(__ldg(temp)) * 1.4426950408889634f;
#pragma unroll
    for (int mt = 0; mt < 2; mt++) {
        const int m = row0 + wm * 32 + mt * 16 + g;
        const int b = m >> 11, nn = m & (SEQ - 1);
#pragma unroll
        for (int nt = 0; nt < 8; nt++) {
            const int n = col0 + wn * 64 + nt * 8 + tig * 2;
            const int part = n >> 10, wc = n & (INNER - 1);
            const int head = wc >> 6, dd = wc & (DH - 1);
            const int bhx = b * HEADS + head, dp = dd >> 1;
#pragma unroll
            for (int slot = 0; slot < 2; slot++) {
                float v0 = acc[mt][nt][slot*2], v1 = acc[mt][nt][slot*2+1];
                if (part == 0) { v0 *= scale; v1 *= scale; }
                const uint32 pk = cvt_h2(v0, v1);
                const int row = nn + slot * 8;
                if (part == 0)      g_q[bhx][row][dp] = pk;
                else if (part == 1) g_k[bhx][row][dp] = pk;
                else                g_v[bhx][row][dp] = pk;
            }
        }
    }
}

// ---------------- kernel 2: flash attention (fp16, ex2.f16x2, MMA row-sums) -
__device__ __forceinline__ void attn_stage_k(uint32 kb, int bh, int j0) {
    const int t = threadIdx.x;
#pragma unroll
    for (int i = 0; i < 2; i++) {
        int cid = t + i * 256;
        int r = cid >> 3, cb = cid & 7;
        cpa16(kb + swz((uint32)(r * 128 + cb * 16)), &g_k[bh][j0 + r][cb * 4]);
    }
}
__device__ __forceinline__ void attn_stage_v(uint32 vb, int bh, int j0) {
    const int t = threadIdx.x;
#pragma unroll
    for (int i = 0; i < 2; i++) {
        int cid = t + i * 256;
        int r = cid >> 3, cb = cid & 7;
        cpa16(vb + swz((uint32)(r * 128 + cb * 16)), &g_vT[bh][r][(j0 >> 1) + cb * 4]);
    }
}

__global__ __launch_bounds__(256, 1) void attn_kernel() {
    __shared__ __align__(128) uint32 sk[2][64][32];   // 16KB (2 buffers)
    __shared__ __align__(128) uint32 sv[2][64][32];   // 16KB
    const int t = threadIdx.x, lane = t & 31, warp = t >> 5;
    const int g = lane >> 2, tig = lane & 3;
    const int n0 = blockIdx.x * 128, bh = blockIdx.y;
    const int qrow = n0 + warp * 16;
    const uint32 kb0 = smem_u32(sk), vb0 = smem_u32(sv);
    const uint32 ONES = 0x3C003C00u;                  // half2(1.0, 1.0)

    uint32 qf[4][4];
#pragma unroll
    for (int s = 0; s < 4; s++) {
        qf[s][0] = g_q[bh][qrow + g]    [s*8 + tig];
        qf[s][1] = g_q[bh][qrow + g + 8][s*8 + tig];
        qf[s][2] = g_q[bh][qrow + g]    [s*8 + tig + 4];
        qf[s][3] = g_q[bh][qrow + g + 8][s*8 + tig + 4];
    }

    float o[8][4];
#pragma unroll
    for (int dt = 0; dt < 8; dt++)
#pragma unroll
        for (int e = 0; e < 4; e++) o[dt][e] = 0.f;
    float lacc[4] = {0.f, 0.f, 0.f, 0.f};   // ones-MMA row-sum accumulator

    attn_stage_k(kb0,        bh, 0);  attn_stage_v(vb0,        bh, 0);
    cp_commit();
    attn_stage_k(kb0 + 8192, bh, 64); attn_stage_v(vb0 + 8192, bh, 64);
    cp_commit();

    const int rkl = (lane & 7) + ((lane >> 4) ? 8 : 0);
    const int ckl = ((lane >> 3) & 1) * 16;
    const int ri0 = qrow + g, ri1 = ri0 + 8;

    for (int i = 0; i < SEQ / 64; i++) {
        const int j0 = i * 64;
        const int p = i & 1;
        const uint32 kb = kb0 + p * 8192;
        const uint32 vb = vb0 + p * 8192;

        cp_wait<1>(); __syncthreads();          // K(i)+V(i) ready

        // S = Q K^T   (logits already in log2 domain via q pre-scale)
        float sacc[8][4];
#pragma unroll
        for (int nt = 0; nt < 8; nt++)
#pragma unroll
            for (int e = 0; e < 4; e++) sacc[nt][e] = 0.f;

#pragma unroll
        for (int s = 0; s < 4; s++) {
            uint32 bf[4][4];
#pragma unroll
            for (int pp = 0; pp < 4; pp++)
                ldm4(bf[pp][0], bf[pp][1], bf[pp][2], bf[pp][3],
                     kb + swz((uint32)((pp * 16 + rkl) * 128 + s * 32 + ckl)));
#pragma unroll
            for (int nt = 0; nt < 8; nt++)
                mma_f16(sacc[nt], qf[s][0], qf[s][1], qf[s][2], qf[s][3],
                        bf[nt >> 1][(nt & 1) * 2], bf[nt >> 1][(nt & 1) * 2 + 1]);
        }

        // P = 2^S in fp16 pairs, diag mask via bit-AND, sums via ones-MMA,
        // O += P V  — all per s-step
        const bool dh = ((unsigned)(qrow - j0) < 64u);
#pragma unroll
        for (int s = 0; s < 4; s++) {
            uint32 pa[4];
            pa[0] = h2ex2(cvt_h2(sacc[2*s][0],     sacc[2*s][1]));
            pa[1] = h2ex2(cvt_h2(sacc[2*s][2],     sacc[2*s][3]));
            pa[2] = h2ex2(cvt_h2(sacc[2*s + 1][0], sacc[2*s + 1][1]));
            pa[3] = h2ex2(cvt_h2(sacc[2*s + 1][2], sacc[2*s + 1][3]));
            if (dh) {
                const int c0 = j0 + s * 16 + tig * 2;
                if (c0     == ri0) pa[0] &= 0xFFFF0000u;
                if (c0 + 1 == ri0) pa[0] &= 0x0000FFFFu;
                if (c0     == ri1) pa[1] &= 0xFFFF0000u;
                if (c0 + 1 == ri1) pa[1] &= 0x0000FFFFu;
                if (c0 + 8 == ri0) pa[2] &= 0xFFFF0000u;
                if (c0 + 9 == ri0) pa[2] &= 0x0000FFFFu;
                if (c0 + 8 == ri1) pa[3] &= 0xFFFF0000u;
                if (c0 + 9 == ri1) pa[3] &= 0x0000FFFFu;
            }
            mma_f16(lacc, pa[0], pa[1], pa[2], pa[3], ONES, ONES);
            uint32 vf[4][4];
#pragma unroll
            for (int pp = 0; pp < 4; pp++)
                ldm4(vf[pp][0], vf[pp][1], vf[pp][2], vf[pp][3],
                     vb + swz((uint32)((pp * 16 + rkl) * 128 + s * 32 + ckl)));
#pragma unroll
            for (int dt = 0; dt < 8; dt++)
                mma_f16(o[dt], pa[0], pa[1], pa[2], pa[3],
                        vf[dt >> 1][(dt & 1) * 2], vf[dt >> 1][(dt & 1) * 2 + 1]);
        }

        __syncthreads();                         // all warps done with buffer p
        if (i + 2 < SEQ / 64) {
            attn_stage_k(kb, bh, j0 + 128);
            attn_stage_v(vb, bh, j0 + 128);
        }
        cp_commit();
    }

    const int b = bh >> 4, head = bh & 15;
    const float inv0 = 1.f / lacc[0], inv1 = 1.f / lacc[2];
#pragma unroll
    for (int dt = 0; dt < 8; dt++) {
        const int ip = head * 32 + dt * 4 + tig;
#pragma unroll
        for (int slot = 0; slot < 2; slot++) {
            const float inv = slot ? inv1 : inv0;
            const int m = b * SEQ + qrow + g + slot * 8;
            g_ao[m][ip] = cvt_h2(o[dt][slot*2] * inv, o[dt][slot*2 + 1] * inv);
        }
    }
}

// ---------------- kernel 3: output projection -------------------------------
__global__ __launch_bounds__(256, 2) void out_gemm_kernel(
    const float* __restrict__ bias, float* __restrict__ out)
{
    __shared__ __align__(128) uint32 smp[3][4096];   // 48KB
    const uint32 sbase = smem_u32(smp);
    const int row0 = blockIdx.x * 128, col0 = blockIdx.y * 128;
    const uint32 *A = &g_ao[row0][0], *B = &g_wout[col0][0];
    const int iters = INNER / 32;

    float acc[2][8][4];
#pragma unroll
    for (int i = 0; i < 2; i++)
#pragma unroll
        for (int j = 0; j < 8; j++)
#pragma unroll
            for (int e = 0; e < 4; e++) acc[i][j][e] = 0.f;

    gemm_stage(sbase, 0, A, B, INNER/2, 0); cp_commit();
    gemm_stage(sbase, 1, A, B, INNER/2, 1); cp_commit();

    for (int it = 0; it < iters; it++) {
        cp_wait<1>(); __syncthreads();
        gemm_compute(sbase, it % 3, acc);
        if (it + 2 < iters)
            gemm_stage(sbase, (it + 2) % 3, A, B, INNER/2, it + 2);
        cp_commit();
    }

    const int lane = threadIdx.x & 31, warp = threadIdx.x >> 5;
    const int wm = warp & 3, wn = warp >> 2;
    const int g = lane >> 2, tig = lane & 3;
#pragma unroll
    for (int mt = 0; mt < 2; mt++) {
        const int m = row0 + wm * 32 + mt * 16 + g;
#pragma unroll
        for (int nt = 0; nt < 8; nt++) {
            const int n = col0 + wn * 64 + nt * 8 + tig * 2;
            const float b0 = bias[n], b1 = bias[n + 1];
#pragma unroll
            for (int slot = 0; slot < 2; slot++) {
                float2 r;
                r.x = acc[mt][nt][slot*2]     + b0;
                r.y = acc[mt][nt][slot*2 + 1] + b1;
                *(float2*)&out[(size_t)(m + slot * 8) * DIM + n] = r;
            }
        }
    }
}

// ---------------------------------------------------------------------------
extern "C" void kernel_launch(void* const* d_in, const int* in_sizes, int n_in,
                              void* d_out, int out_size)
{
    const float* x    = (const float*)d_in[0];
    const float* wqkv = (const float*)d_in[1];
    const float* wout = (const float*)d_in[2];
    const float* bout = (const float*)d_in[3];
    const float* temp = (const float*)d_in[4];
    float* out = (float*)d_out;

    pack_x_kernel<<<(MTOT * DIM / 2) / 256, 256>>>(x);
    pack_wT_kernel<<<dim3(DIM / 64, QKVN / 64), 256>>>(wqkv, 0);
    pack_wT_kernel<<<dim3(INNER / 64, DIM / 64), 256>>>(wout, 1);
    qkv_gemm_kernel<<<dim3(MTOT / 128, QKVN / 128), 256>>>(temp);
    vT_kernel<<<dim3(SEQ / 64, BH), 256>>>();
    attn_kernel<<<dim3(SEQ / 128, BH), 256>>>();
    out_gemm_kernel<<<dim3(MTOT / 128, DIM / 128), 256>>>(bout, out);
}

// round 16
// speedup vs baseline: 1.0015x; 1.0015x over previous
#include <cuda_runtime.h>
#include <cuda_fp16.h>
#include <math.h>

#define BATCH 4
#define SEQ   2048
#define DIM   1024
#define HEADS 16
#define DH    64
#define INNER 1024
#define MTOT  (BATCH*SEQ)   // 8192
#define QKVN  (3*INNER)     // 3072
#define BH    (BATCH*HEADS) // 64

typedef unsigned int uint32;

// ---------------- fp16 (half2-packed) scratch -------------------------------
__device__ uint32 g_xp  [MTOT][DIM/2];
__device__ uint32 g_wqkv[QKVN][DIM/2];
__device__ uint32 g_wout[DIM][INNER/2];
__device__ uint32 g_q [BH][SEQ][DH/2];    // pre-scaled by exp(temperature)*log2(e)
__device__ uint32 g_k [BH][SEQ][DH/2];
__device__ uint32 g_v [BH][SEQ][DH/2];
__device__ uint32 g_vT[BH][DH][SEQ/2];
__device__ uint32 g_ao[MTOT][INNER/2];

// ---------------- helpers ---------------------------------------------------
__device__ __forceinline__ uint32 cvt_h2(float x, float y) {
    __half2 h = __floats2half2_rn(x, y);
    return *reinterpret_cast<uint32*>(&h);
}

__device__ __forceinline__ uint32 h2ex2(uint32 x) {
    uint32 r;
    asm volatile("ex2.approx.f16x2 %0, %1;\n" : "=r"(r) : "r"(x));
    return r;
}

__device__ __forceinline__ void mma_f16(float* c, uint32 a0, uint32 a1, uint32 a2,
                                        uint32 a3, uint32 b0, uint32 b1) {
    asm volatile(
        "mma.sync.aligned.m16n8k16.row.col.f32.f16.f16.f32 "
        "{%0,%1,%2,%3},{%4,%5,%6,%7},{%8,%9},{%0,%1,%2,%3};\n"
        : "+f"(c[0]), "+f"(c[1]), "+f"(c[2]), "+f"(c[3])
        : "r"(a0), "r"(a1), "r"(a2), "r"(a3), "r"(b0), "r"(b1));
}

__device__ __forceinline__ uint32 smem_u32(const void* p) {
    uint32 a;
    asm("{ .reg .u64 t; cvta.to.shared.u64 t, %1; cvt.u32.u64 %0, t; }"
        : "=r"(a) : "l"(p));
    return a;
}

__device__ __forceinline__ uint32 swz(uint32 o) { return o ^ ((o >> 3) & 0x70); }

__device__ __forceinline__ void cpa16(uint32 dst, const void* src) {
    asm volatile("cp.async.cg.shared.global [%0], [%1], 16;\n" :: "r"(dst), "l"(src));
}
__device__ __forceinline__ void cp_commit() { asm volatile("cp.async.commit_group;\n"); }
template<int N> __device__ __forceinline__ void cp_wait() {
    asm volatile("cp.async.wait_group %0;\n" :: "n"(N));
}

__device__ __forceinline__ void ldm4(uint32& r0, uint32& r1, uint32& r2, uint32& r3,
                                     uint32 addr) {
    asm volatile("ldmatrix.sync.aligned.m8n8.x4.shared.b16 {%0,%1,%2,%3},[%4];\n"
        : "=r"(r0), "=r"(r1), "=r"(r2), "=r"(r3) : "r"(addr));
}

// ---------------- prep kernels ----------------------------------------------
__global__ __launch_bounds__(256) void pack_x_kernel(const float* __restrict__ x) {
    int i = blockIdx.x * 256 + threadIdx.x;
    float2 v = ((const float2*)x)[i];
    (&g_xp[0][0])[i] = cvt_h2(v.x, v.y);
}

__global__ __launch_bounds__(256) void pack_wT_kernel(const float* __restrict__ w, int mode) {
    __shared__ float sm[64][65];
    const int K = mode ? INNER : DIM;
    const int N = mode ? DIM : QKVN;
    uint32* __restrict__ dst = mode ? &g_wout[0][0] : &g_wqkv[0][0];
    const int k0 = blockIdx.x * 64, n0 = blockIdx.y * 64;
    const int t = threadIdx.x;
#pragma unroll
    for (int it = 0; it < 4; it++) {
        int idx = t + it * 256;
        int r = idx >> 4, c = (idx & 15) * 4;
        float4 f = *(const float4*)&w[(size_t)(k0 + r) * N + n0 + c];
        sm[r][c] = f.x; sm[r][c+1] = f.y; sm[r][c+2] = f.z; sm[r][c+3] = f.w;
    }
    __syncthreads();
#pragma unroll
    for (int it = 0; it < 8; it++) {
        int idx = t + it * 256;
        int n = idx >> 5, kp = idx & 31;
        dst[(size_t)(n0 + n) * (K/2) + (k0 >> 1) + kp] = cvt_h2(sm[2*kp][n], sm[2*kp+1][n]);
    }
}

__global__ __launch_bounds__(256) void vT_kernel() {
    __shared__ uint32 sm[64][36];
    const int n0 = blockIdx.x * 64, bhi = blockIdx.y;
    const int t = threadIdx.x;
#pragma unroll
    for (int it = 0; it < 2; it++) {
        int idx = t + it * 256;
        int r = idx >> 3, c = (idx & 7) * 4;
        *(uint4*)&sm[r][c] = *(const uint4*)&g_v[bhi][n0 + r][c];
    }
    __syncthreads();
#pragma unroll
    for (int it = 0; it < 8; it++) {
        int idx = t + it * 256;              // 64*32 = 2048
        int d = idx >> 5, npl = idx & 31;
        uint32 w0 = sm[2*npl][d >> 1];
        uint32 w1 = sm[2*npl + 1][d >> 1];
        uint32 o = (d & 1) ? __byte_perm(w0, w1, 0x7632) : __byte_perm(w0, w1, 0x5410);
        g_vT[bhi][d][(n0 >> 1) + npl] = o;
    }
}

// ---------------- pipelined GEMM (128x128 tile, BK=32, fp16, 3-stage) -------
__device__ __forceinline__ void gemm_stage(uint32 sbase, int stage,
    const uint32* __restrict__ A, const uint32* __restrict__ B, int k2, int kc)
{
    const int t = threadIdx.x;
#pragma unroll
    for (int i = 0; i < 4; i++) {
        int cid = t + i * 256;          // 0..1023
        int tile = cid >> 9;            // 0=A 1=B
        int w = cid & 511;
        int r = w >> 2, c = w & 3;
        const uint32* src = (tile ? B : A) + (size_t)r * k2 + kc * 16 + c * 4;
        cpa16(sbase + stage * 16384 + tile * 8192 + swz((uint32)(r * 64 + c * 16)), src);
    }
}

__device__ __forceinline__ void gemm_compute(uint32 sbase, int stage,
                                             float (&acc)[2][8][4])
{
    const int lane = threadIdx.x & 31, warp = threadIdx.x >> 5;
    const int wm = warp & 3, wn = warp >> 2;
    const uint32 pb = sbase + stage * 16384;

    const int ra = wm * 32 + (lane & 15);
    const int ca = (lane >> 4) * 16;
    const int rbl = (lane & 7) + ((lane >> 4) ? 8 : 0);
    const int cbl = ((lane >> 3) & 1) * 16;

#pragma unroll
    for (int s = 0; s < 2; s++) {
        uint32 a[2][4];
#pragma unroll
        for (int mt = 0; mt < 2; mt++)
            ldm4(a[mt][0], a[mt][1], a[mt][2], a[mt][3],
                 pb + swz((uint32)((ra + mt * 16) * 64 + s * 32 + ca)));
        uint32 bf[4][4];
#pragma unroll
        for (int p = 0; p < 4; p++)
            ldm4(bf[p][0], bf[p][1], bf[p][2], bf[p][3],
                 pb + 8192 + swz((uint32)((wn * 64 + p * 16 + rbl) * 64 + s * 32 + cbl)));
#pragma unroll
        for (int mt = 0; mt < 2; mt++)
#pragma unroll
            for (int nt = 0; nt < 8; nt++)
                mma_f16(acc[mt][nt], a[mt][0], a[mt][1], a[mt][2], a[mt][3],
                        bf[nt >> 1][(nt & 1) * 2], bf[nt >> 1][(nt & 1) * 2 + 1]);
    }
}

// ---------------- kernel 1: QKV projection ----------------------------------
__global__ __launch_bounds__(256, 2) void qkv_gemm_kernel(const float* __restrict__ temp) {
    __shared__ __align__(128) uint32 smp[3][4096];   // 48KB
    const uint32 sbase = smem_u32(smp);
    const int row0 = blockIdx.x * 128, col0 = blockIdx.y * 128;
    const uint32 *A = &g_xp[row0][0], *B = &g_wqkv[col0][0];
    const int iters = DIM / 32;

    float acc[2][8][4];
#pragma unroll
    for (int i = 0; i < 2; i++)
#pragma unroll
        for (int j = 0; j < 8; j++)
#pragma unroll
            for (int e = 0; e < 4; e++) acc[i][j][e] = 0.f;

    gemm_stage(sbase, 0, A, B, DIM/2, 0); cp_commit();
    gemm_stage(sbase, 1, A, B, DIM/2, 1); cp_commit();

    for (int it = 0; it < iters; it++) {
        cp_wait<1>(); __syncthreads();
        gemm_compute(sbase, it % 3, acc);
        if (it + 2 < iters)
            gemm_stage(sbase, (it + 2) % 3, A, B, DIM/2, it + 2);
        cp_commit();
    }

    const int lane = threadIdx.x & 31, warp = threadIdx.x >> 5;
    const int wm = warp & 3, wn = warp >> 2;
    const int g = lane >> 2, tig = lane & 3;
    // q pre-scale folds softmax scale AND log2(e) so attention uses ex2 directly
    const float scale = __expf(__ldg(temp)) * 1.4426950408889634f;
#pragma unroll
    for (int mt = 0; mt < 2; mt++) {
        const int m = row0 + wm * 32 + mt * 16 + g;
        const int b = m >> 11, nn = m & (SEQ - 1);
#pragma unroll
        for (int nt = 0; nt < 8; nt++) {
            const int n = col0 + wn * 64 + nt * 8 + tig * 2;
            const int part = n >> 10, wc = n & (INNER - 1);
            const int head = wc >> 6, dd = wc & (DH - 1);
            const int bhx = b * HEADS + head, dp = dd >> 1;
#pragma unroll
            for (int slot = 0; slot < 2; slot++) {
                float v0 = acc[mt][nt][slot*2], v1 = acc[mt][nt][slot*2+1];
                if (part == 0) { v0 *= scale; v1 *= scale; }
                const uint32 pk = cvt_h2(v0, v1);
                const int row = nn + slot * 8;
                if (part == 0)      g_q[bhx][row][dp] = pk;
                else if (part == 1) g_k[bhx][row][dp] = pk;
                else                g_v[bhx][row][dp] = pk;
            }
        }
    }
}

// ---------------- kernel 2: flash attention (fp16, ex2.f16x2, MMA row-sums) -
__device__ __forceinline__ void attn_stage_k(uint32 kb, int bh, int j0) {
    const int t = threadIdx.x;
#pragma unroll
    for (int i = 0; i < 2; i++) {
        int cid = t + i * 256;
        int r = cid >> 3, cb = cid & 7;
        cpa16(kb + swz((uint32)(r * 128 + cb * 16)), &g_k[bh][j0 + r][cb * 4]);
    }
}
__device__ __forceinline__ void attn_stage_v(uint32 vb, int bh, int j0) {
    const int t = threadIdx.x;
#pragma unroll
    for (int i = 0; i < 2; i++) {
        int cid = t + i * 256;
        int r = cid >> 3, cb = cid & 7;
        cpa16(vb + swz((uint32)(r * 128 + cb * 16)), &g_vT[bh][r][(j0 >> 1) + cb * 4]);
    }
}

__global__ __launch_bounds__(256, 1) void attn_kernel() {
    __shared__ __align__(128) uint32 sk[2][64][32];   // 16KB (2 buffers)
    __shared__ __align__(128) uint32 sv[2][64][32];   // 16KB
    const int t = threadIdx.x, lane = t & 31, warp = t >> 5;
    const int g = lane >> 2, tig = lane & 3;
    const int n0 = blockIdx.x * 128, bh = blockIdx.y;
    const int qrow = n0 + warp * 16;
    const uint32 kb0 = smem_u32(sk), vb0 = smem_u32(sv);
    const uint32 ONES = 0x3C003C00u;                  // half2(1.0, 1.0)

    uint32 qf[4][4];
#pragma unroll
    for (int s = 0; s < 4; s++) {
        qf[s][0] = g_q[bh][qrow + g]    [s*8 + tig];
        qf[s][1] = g_q[bh][qrow + g + 8][s*8 + tig];
        qf[s][2] = g_q[bh][qrow + g]    [s*8 + tig + 4];
        qf[s][3] = g_q[bh][qrow + g + 8][s*8 + tig + 4];
    }

    float o[8][4];
#pragma unroll
    for (int dt = 0; dt < 8; dt++)
#pragma unroll
        for (int e = 0; e < 4; e++) o[dt][e] = 0.f;
    float lacc[4] = {0.f, 0.f, 0.f, 0.f};   // ones-MMA row-sum accumulator

    attn_stage_k(kb0,        bh, 0);  attn_stage_v(vb0,        bh, 0);
    cp_commit();
    attn_stage_k(kb0 + 8192, bh, 64); attn_stage_v(vb0 + 8192, bh, 64);
    cp_commit();

    const int rkl = (lane & 7) + ((lane >> 4) ? 8 : 0);
    const int ckl = ((lane >> 3) & 1) * 16;
    const int ri0 = qrow + g, ri1 = ri0 + 8;

    for (int i = 0; i < SEQ / 64; i++) {
        const int j0 = i * 64;
        const int p = i & 1;
        const uint32 kb = kb0 + p * 8192;
        const uint32 vb = vb0 + p * 8192;

        cp_wait<1>(); __syncthreads();          // K(i)+V(i) ready

        // S = Q K^T   (logits already in log2 domain via q pre-scale)
        float sacc[8][4];
#pragma unroll
        for (int nt = 0; nt < 8; nt++)
#pragma unroll
            for (int e = 0; e < 4; e++) sacc[nt][e] = 0.f;

#pragma unroll
        for (int s = 0; s < 4; s++) {
            uint32 bf[4][4];
#pragma unroll
            for (int pp = 0; pp < 4; pp++)
                ldm4(bf[pp][0], bf[pp][1], bf[pp][2], bf[pp][3],
                     kb + swz((uint32)((pp * 16 + rkl) * 128 + s * 32 + ckl)));
#pragma unroll
            for (int nt = 0; nt < 8; nt++)
                mma_f16(sacc[nt], qf[s][0], qf[s][1], qf[s][2], qf[s][3],
                        bf[nt >> 1][(nt & 1) * 2], bf[nt >> 1][(nt & 1) * 2 + 1]);
        }

        // P = 2^S in fp16 pairs, diag mask via bit-AND, sums via ones-MMA,
        // O += P V  — all per s-step
        const bool dh = ((unsigned)(qrow - j0) < 64u);
#pragma unroll
        for (int s = 0; s < 4; s++) {
            uint32 pa[4];
            pa[0] = h2ex2(cvt_h2(sacc[2*s][0],     sacc[2*s][1]));
            pa[1] = h2ex2(cvt_h2(sacc[2*s][2],     sacc[2*s][3]));
            pa[2] = h2ex2(cvt_h2(sacc[2*s + 1][0], sacc[2*s + 1][1]));
            pa[3] = h2ex2(cvt_h2(sacc[2*s + 1][2], sacc[2*s + 1][3]));
            if (dh) {
                const int c0 = j0 + s * 16 + tig * 2;
                if (c0     == ri0) pa[0] &= 0xFFFF0000u;
                if (c0 + 1 == ri0) pa[0] &= 0x0000FFFFu;
                if (c0     == ri1) pa[1] &= 0xFFFF0000u;
                if (c0 + 1 == ri1) pa[1] &= 0x0000FFFFu;
                if (c0 + 8 == ri0) pa[2] &= 0xFFFF0000u;
                if (c0 + 9 == ri0) pa[2] &= 0x0000FFFFu;
                if (c0 + 8 == ri1) pa[3] &= 0xFFFF0000u;
                if (c0 + 9 == ri1) pa[3] &= 0x0000FFFFu;
            }
            mma_f16(lacc, pa[0], pa[1], pa[2], pa[3], ONES, ONES);
            uint32 vf[4][4];
#pragma unroll
            for (int pp = 0; pp < 4; pp++)
                ldm4(vf[pp][0], vf[pp][1], vf[pp][2], vf[pp][3],
                     vb + swz((uint32)((pp * 16 + rkl) * 128 + s * 32 + ckl)));
#pragma unroll
            for (int dt = 0; dt < 8; dt++)
                mma_f16(o[dt], pa[0], pa[1], pa[2], pa[3],
                        vf[dt >> 1][(dt & 1) * 2], vf[dt >> 1][(dt & 1) * 2 + 1]);
        }

        __syncthreads();                         // all warps done with buffer p
        if (i + 2 < SEQ / 64) {
            attn_stage_k(kb, bh, j0 + 128);
            attn_stage_v(vb, bh, j0 + 128);
        }
        cp_commit();
    }

    const int b = bh >> 4, head = bh & 15;
    const float inv0 = 1.f / lacc[0], inv1 = 1.f / lacc[2];
#pragma unroll
    for (int dt = 0; dt < 8; dt++) {
        const int ip = head * 32 + dt * 4 + tig;
#pragma unroll
        for (int slot = 0; slot < 2; slot++) {
            const float inv = slot ? inv1 : inv0;
            const int m = b * SEQ + qrow + g + slot * 8;
            g_ao[m][ip] = cvt_h2(o[dt][slot*2] * inv, o[dt][slot*2 + 1] * inv);
        }
    }
}

// ---------------- kernel 3: output projection -------------------------------
__global__ __launch_bounds__(256, 2) void out_gemm_kernel(
    const float* __restrict__ bias, float* __restrict__ out)
{
    __shared__ __align__(128) uint32 smp[3][4096];   // 48KB
    const uint32 sbase = smem_u32(smp);
    const int row0 = blockIdx.x * 128, col0 = blockIdx.y * 128;
    const uint32 *A = &g_ao[row0][0], *B = &g_wout[col0][0];
    const int iters = INNER / 32;

    float acc[2][8][4];
#pragma unroll
    for (int i = 0; i < 2; i++)
#pragma unroll
        for (int j = 0; j < 8; j++)
#pragma unroll
            for (int e = 0; e < 4; e++) acc[i][j][e] = 0.f;

    gemm_stage(sbase, 0, A, B, INNER/2, 0); cp_commit();
    gemm_stage(sbase, 1, A, B, INNER/2, 1); cp_commit();

    for (int it = 0; it < iters; it++) {
        cp_wait<1>(); __syncthreads();
        gemm_compute(sbase, it % 3, acc);
        if (it + 2 < iters)
            gemm_stage(sbase, (it + 2) % 3, A, B, INNER/2, it + 2);
        cp_commit();
    }

    const int lane = threadIdx.x & 31, warp = threadIdx.x >> 5;
    const int wm = warp & 3, wn = warp >> 2;
    const int g = lane >> 2, tig = lane & 3;
#pragma unroll
    for (int mt = 0; mt < 2; mt++) {
        const int m = row0 + wm * 32 + mt * 16 + g;
#pragma unroll
        for (int nt = 0; nt < 8; nt++) {
            const int n = col0 + wn * 64 + nt * 8 + tig * 2;
            const float b0 = bias[n], b1 = bias[n + 1];
#pragma unroll
            for (int slot = 0; slot < 2; slot++) {
                float2 r;
                r.x = acc[mt][nt][slot*2]     + b0;
                r.y = acc[mt][nt][slot*2 + 1] + b1;
                *(float2*)&out[(size_t)(m + slot * 8) * DIM + n] = r;
            }
        }
    }
}

// ---------------------------------------------------------------------------
extern "C" void kernel_launch(void* const* d_in, const int* in_sizes, int n_in,
                              void* d_out, int out_size)
{
    const float* x    = (const float*)d_in[0];
    const float* wqkv = (const float*)d_in[1];
    const float* wout = (const float*)d_in[2];
    const float* bout = (const float*)d_in[3];
    const float* temp = (const float*)d_in[4];
    float* out = (float*)d_out;

    pack_x_kernel<<<(MTOT * DIM / 2) / 256, 256>>>(x);
    pack_wT_kernel<<<dim3(DIM / 64, QKVN / 64), 256>>>(wqkv, 0);
    pack_wT_kernel<<<dim3(INNER / 64, DIM / 64), 256>>>(wout, 1);
    qkv_gemm_kernel<<<dim3(MTOT / 128, QKVN / 128), 256>>>(temp);
    vT_kernel<<<dim3(SEQ / 64, BH), 256>>>();
    attn_kernel<<<dim3(SEQ / 128, BH), 256>>>();
    out_gemm_kernel<<<dim3(MTOT / 128, DIM / 128), 256>>>(bout, out);
}

// round 17
// speedup vs baseline: 1.0049x; 1.0034x over previous
#include <cuda_runtime.h>
#include <cuda_fp16.h>
#include <math.h>

#define BATCH 4
#define SEQ   2048
#define DIM   1024
#define HEADS 16
#define DH    64
#define INNER 1024
#define MTOT  (BATCH*SEQ)   // 8192
#define QKVN  (3*INNER)     // 3072
#define BH    (BATCH*HEADS) // 64

typedef unsigned int uint32;

// ---------------- fp16 (half2-packed) scratch -------------------------------
__device__ uint32 g_xp  [MTOT][DIM/2];
__device__ uint32 g_wqkv[QKVN][DIM/2];
__device__ uint32 g_wout[DIM][INNER/2];
__device__ uint32 g_q [BH][SEQ][DH/2];    // pre-scaled by exp(temperature)*log2(e)
__device__ uint32 g_k [BH][SEQ][DH/2];
__device__ uint32 g_v [BH][SEQ][DH/2];
__device__ uint32 g_vT[BH][DH][SEQ/2];
__device__ uint32 g_ao[MTOT][INNER/2];

// ---------------- helpers ---------------------------------------------------
__device__ __forceinline__ uint32 cvt_h2(float x, float y) {
    __half2 h = __floats2half2_rn(x, y);
    return *reinterpret_cast<uint32*>(&h);
}

__device__ __forceinline__ uint32 h2ex2(uint32 x) {
    uint32 r;
    asm volatile("ex2.approx.f16x2 %0, %1;\n" : "=r"(r) : "r"(x));
    return r;
}

__device__ __forceinline__ void mma_f16(float* c, uint32 a0, uint32 a1, uint32 a2,
                                        uint32 a3, uint32 b0, uint32 b1) {
    asm volatile(
        "mma.sync.aligned.m16n8k16.row.col.f32.f16.f16.f32 "
        "{%0,%1,%2,%3},{%4,%5,%6,%7},{%8,%9},{%0,%1,%2,%3};\n"
        : "+f"(c[0]), "+f"(c[1]), "+f"(c[2]), "+f"(c[3])
        : "r"(a0), "r"(a1), "r"(a2), "r"(a3), "r"(b0), "r"(b1));
}

__device__ __forceinline__ uint32 smem_u32(const void* p) {
    uint32 a;
    asm("{ .reg .u64 t; cvta.to.shared.u64 t, %1; cvt.u32.u64 %0, t; }"
        : "=r"(a) : "l"(p));
    return a;
}

__device__ __forceinline__ uint32 swz(uint32 o) { return o ^ ((o >> 3) & 0x70); }

__device__ __forceinline__ void cpa16(uint32 dst, const void* src) {
    asm volatile("cp.async.cg.shared.global [%0], [%1], 16;\n" :: "r"(dst), "l"(src));
}
__device__ __forceinline__ void cp_commit() { asm volatile("cp.async.commit_group;\n"); }
template<int N> __device__ __forceinline__ void cp_wait() {
    asm volatile("cp.async.wait_group %0;\n" :: "n"(N));
}

__device__ __forceinline__ void ldm4(uint32& r0, uint32& r1, uint32& r2, uint32& r3,
                                     uint32 addr) {
    asm volatile("ldmatrix.sync.aligned.m8n8.x4.shared.b16 {%0,%1,%2,%3},[%4];\n"
        : "=r"(r0), "=r"(r1), "=r"(r2), "=r"(r3) : "r"(addr));
}

// ---------------- prep kernels ----------------------------------------------
__global__ __launch_bounds__(256) void pack_x_kernel(const float* __restrict__ x) {
    int i = blockIdx.x * 256 + threadIdx.x;
    float2 v = ((const float2*)x)[i];
    (&g_xp[0][0])[i] = cvt_h2(v.x, v.y);
}

__global__ __launch_bounds__(256) void pack_wT_kernel(const float* __restrict__ w, int mode) {
    __shared__ float sm[64][65];
    const int K = mode ? INNER : DIM;
    const int N = mode ? DIM : QKVN;
    uint32* __restrict__ dst = mode ? &g_wout[0][0] : &g_wqkv[0][0];
    const int k0 = blockIdx.x * 64, n0 = blockIdx.y * 64;
    const int t = threadIdx.x;
#pragma unroll
    for (int it = 0; it < 4; it++) {
        int idx = t + it * 256;
        int r = idx >> 4, c = (idx & 15) * 4;
        float4 f = *(const float4*)&w[(size_t)(k0 + r) * N + n0 + c];
        sm[r][c] = f.x; sm[r][c+1] = f.y; sm[r][c+2] = f.z; sm[r][c+3] = f.w;
    }
    __syncthreads();
#pragma unroll
    for (int it = 0; it < 8; it++) {
        int idx = t + it * 256;
        int n = idx >> 5, kp = idx & 31;
        dst[(size_t)(n0 + n) * (K/2) + (k0 >> 1) + kp] = cvt_h2(sm[2*kp][n], sm[2*kp+1][n]);
    }
}

__global__ __launch_bounds__(256) void vT_kernel() {
    __shared__ uint32 sm[64][36];
    const int n0 = blockIdx.x * 64, bhi = blockIdx.y;
    const int t = threadIdx.x;
#pragma unroll
    for (int it = 0; it < 2; it++) {
        int idx = t + it * 256;
        int r = idx >> 3, c = (idx & 7) * 4;
        *(uint4*)&sm[r][c] = *(const uint4*)&g_v[bhi][n0 + r][c];
    }
    __syncthreads();
#pragma unroll
    for (int it = 0; it < 8; it++) {
        int idx = t + it * 256;              // 64*32 = 2048
        int d = idx >> 5, npl = idx & 31;
        uint32 w0 = sm[2*npl][d >> 1];
        uint32 w1 = sm[2*npl + 1][d >> 1];
        uint32 o = (d & 1) ? __byte_perm(w0, w1, 0x7632) : __byte_perm(w0, w1, 0x5410);
        g_vT[bhi][d][(n0 >> 1) + npl] = o;
    }
}

// ---------------- pipelined GEMM (128x128 tile, BK=32, fp16, 3-stage) -------
__device__ __forceinline__ void gemm_stage(uint32 sbase, int stage,
    const uint32* __restrict__ A, const uint32* __restrict__ B, int k2, int kc)
{
    const int t = threadIdx.x;
#pragma unroll
    for (int i = 0; i < 4; i++) {
        int cid = t + i * 256;          // 0..1023
        int tile = cid >> 9;            // 0=A 1=B
        int w = cid & 511;
        int r = w >> 2, c = w & 3;
        const uint32* src = (tile ? B : A) + (size_t)r * k2 + kc * 16 + c * 4;
        cpa16(sbase + stage * 16384 + tile * 8192 + swz((uint32)(r * 64 + c * 16)), src);
    }
}

__device__ __forceinline__ void gemm_compute(uint32 sbase, int stage,
                                             float (&acc)[2][8][4])
{
    const int lane = threadIdx.x & 31, warp = threadIdx.x >> 5;
    const int wm = warp & 3, wn = warp >> 2;
    const uint32 pb = sbase + stage * 16384;

    const int ra = wm * 32 + (lane & 15);
    const int ca = (lane >> 4) * 16;
    const int rbl = (lane & 7) + ((lane >> 4) ? 8 : 0);
    const int cbl = ((lane >> 3) & 1) * 16;

#pragma unroll
    for (int s = 0; s < 2; s++) {
        uint32 a[2][4];
#pragma unroll
        for (int mt = 0; mt < 2; mt++)
            ldm4(a[mt][0], a[mt][1], a[mt][2], a[mt][3],
                 pb + swz((uint32)((ra + mt * 16) * 64 + s * 32 + ca)));
        uint32 bf[4][4];
#pragma unroll
        for (int p = 0; p < 4; p++)
            ldm4(bf[p][0], bf[p][1], bf[p][2], bf[p][3],
                 pb + 8192 + swz((uint32)((wn * 64 + p * 16 + rbl) * 64 + s * 32 + cbl)));
#pragma unroll
        for (int mt = 0; mt < 2; mt++)
#pragma unroll
            for (int nt = 0; nt < 8; nt++)
                mma_f16(acc[mt][nt], a[mt][0], a[mt][1], a[mt][2], a[mt][3],
                        bf[nt >> 1][(nt & 1) * 2], bf[nt >> 1][(nt & 1) * 2 + 1]);
    }
}

// ---------------- kernel 1: QKV projection ----------------------------------
__global__ __launch_bounds__(256, 2) void qkv_gemm_kernel(const float* __restrict__ temp) {
    __shared__ __align__(128) uint32 smp[3][4096];   // 48KB
    const uint32 sbase = smem_u32(smp);
    const int row0 = blockIdx.x * 128, col0 = blockIdx.y * 128;
    const uint32 *A = &g_xp[row0][0], *B = &g_wqkv[col0][0];
    const int iters = DIM / 32;

    float acc[2][8][4];
#pragma unroll
    for (int i = 0; i < 2; i++)
#pragma unroll
        for (int j = 0; j < 8; j++)
#pragma unroll
            for (int e = 0; e < 4; e++) acc[i][j][e] = 0.f;

    gemm_stage(sbase, 0, A, B, DIM/2, 0); cp_commit();
    gemm_stage(sbase, 1, A, B, DIM/2, 1); cp_commit();

    for (int it = 0; it < iters; it++) {
        cp_wait<1>(); __syncthreads();
        gemm_compute(sbase, it % 3, acc);
        if (it + 2 < iters)
            gemm_stage(sbase, (it + 2) % 3, A, B, DIM/2, it + 2);
        cp_commit();
    }

    const int lane = threadIdx.x & 31, warp = threadIdx.x >> 5;
    const int wm = warp & 3, wn = warp >> 2;
    const int g = lane >> 2, tig = lane & 3;
    // q pre-scale folds softmax scale AND log2(e) so attention uses ex2 directly
    const float scale = __expf(__ldg(temp)) * 1.4426950408889634f;
#pragma unroll
    for (int mt = 0; mt < 2; mt++) {
        const int m = row0 + wm * 32 + mt * 16 + g;
        const int b = m >> 11, nn = m & (SEQ - 1);
#pragma unroll
        for (int nt = 0; nt < 8; nt++) {
            const int n = col0 + wn * 64 + nt * 8 + tig * 2;
            const int part = n >> 10, wc = n & (INNER - 1);
            const int head = wc >> 6, dd = wc & (DH - 1);
            const int bhx = b * HEADS + head, dp = dd >> 1;
#pragma unroll
            for (int slot = 0; slot < 2; slot++) {
                float v0 = acc[mt][nt][slot*2], v1 = acc[mt][nt][slot*2+1];
                if (part == 0) { v0 *= scale; v1 *= scale; }
                const uint32 pk = cvt_h2(v0, v1);
                const int row = nn + slot * 8;
                if (part == 0)      g_q[bhx][row][dp] = pk;
                else if (part == 1) g_k[bhx][row][dp] = pk;
                else                g_v[bhx][row][dp] = pk;
            }
        }
    }
}

// ---------------- kernel 2: flash attention (fp16, ex2.f16x2, MMA row-sums) -
__device__ __forceinline__ void attn_stage_k(uint32 kb, int bh, int j0) {
    const int t = threadIdx.x;
#pragma unroll
    for (int i = 0; i < 2; i++) {
        int cid = t + i * 256;
        int r = cid >> 3, cb = cid & 7;
        cpa16(kb + swz((uint32)(r * 128 + cb * 16)), &g_k[bh][j0 + r][cb * 4]);
    }
}
__device__ __forceinline__ void attn_stage_v(uint32 vb, int bh, int j0) {
    const int t = threadIdx.x;
#pragma unroll
    for (int i = 0; i < 2; i++) {
        int cid = t + i * 256;
        int r = cid >> 3, cb = cid & 7;
        cpa16(vb + swz((uint32)(r * 128 + cb * 16)), &g_vT[bh][r][(j0 >> 1) + cb * 4]);
    }
}

__global__ __launch_bounds__(256, 1) void attn_kernel() {
    __shared__ __align__(128) uint32 sk[2][64][32];   // 16KB (2 buffers)
    __shared__ __align__(128) uint32 sv[2][64][32];   // 16KB
    const int t = threadIdx.x, lane = t & 31, warp = t >> 5;
    const int g = lane >> 2, tig = lane & 3;
    const int n0 = blockIdx.x * 128, bh = blockIdx.y;
    const int qrow = n0 + warp * 16;
    const uint32 kb0 = smem_u32(sk), vb0 = smem_u32(sv);
    const uint32 ONES = 0x3C003C00u;                  // half2(1.0, 1.0)

    uint32 qf[4][4];
#pragma unroll
    for (int s = 0; s < 4; s++) {
        qf[s][0] = g_q[bh][qrow + g]    [s*8 + tig];
        qf[s][1] = g_q[bh][qrow + g + 8][s*8 + tig];
        qf[s][2] = g_q[bh][qrow + g]    [s*8 + tig + 4];
        qf[s][3] = g_q[bh][qrow + g + 8][s*8 + tig + 4];
    }

    float o[8][4];
#pragma unroll
    for (int dt = 0; dt < 8; dt++)
#pragma unroll
        for (int e = 0; e < 4; e++) o[dt][e] = 0.f;
    float lacc[4] = {0.f, 0.f, 0.f, 0.f};   // ones-MMA row-sum accumulator

    attn_stage_k(kb0,        bh, 0);  attn_stage_v(vb0,        bh, 0);
    cp_commit();
    attn_stage_k(kb0 + 8192, bh, 64); attn_stage_v(vb0 + 8192, bh, 64);
    cp_commit();

    const int rkl = (lane & 7) + ((lane >> 4) ? 8 : 0);
    const int ckl = ((lane >> 3) & 1) * 16;
    const int ri0 = qrow + g, ri1 = ri0 + 8;

    for (int i = 0; i < SEQ / 64; i++) {
        const int j0 = i * 64;
        const int p = i & 1;
        const uint32 kb = kb0 + p * 8192;
        const uint32 vb = vb0 + p * 8192;

        cp_wait<1>(); __syncthreads();          // K(i)+V(i) ready

        // S = Q K^T   (logits already in log2 domain via q pre-scale)
        float sacc[8][4];
#pragma unroll
        for (int nt = 0; nt < 8; nt++)
#pragma unroll
            for (int e = 0; e < 4; e++) sacc[nt][e] = 0.f;

#pragma unroll
        for (int s = 0; s < 4; s++) {
            uint32 bf[4][4];
#pragma unroll
            for (int pp = 0; pp < 4; pp++)
                ldm4(bf[pp][0], bf[pp][1], bf[pp][2], bf[pp][3],
                     kb + swz((uint32)((pp * 16 + rkl) * 128 + s * 32 + ckl)));
#pragma unroll
            for (int nt = 0; nt < 8; nt++)
                mma_f16(sacc[nt], qf[s][0], qf[s][1], qf[s][2], qf[s][3],
                        bf[nt >> 1][(nt & 1) * 2], bf[nt >> 1][(nt & 1) * 2 + 1]);
        }

        // P = 2^S in fp16 pairs, diag mask via bit-AND, sums via ones-MMA,
        // O += P V  — all per s-step
        const bool dh = ((unsigned)(qrow - j0) < 64u);
#pragma unroll
        for (int s = 0; s < 4; s++) {
            uint32 pa[4];
            pa[0] = h2ex2(cvt_h2(sacc[2*s][0],     sacc[2*s][1]));
            pa[1] = h2ex2(cvt_h2(sacc[2*s][2],     sacc[2*s][3]));
            pa[2] = h2ex2(cvt_h2(sacc[2*s + 1][0], sacc[2*s + 1][1]));
            pa[3] = h2ex2(cvt_h2(sacc[2*s + 1][2], sacc[2*s + 1][3]));
            if (dh) {
                const int c0 = j0 + s * 16 + tig * 2;
                if (c0     == ri0) pa[0] &= 0xFFFF0000u;
                if (c0 + 1 == ri0) pa[0] &= 0x0000FFFFu;
                if (c0     == ri1) pa[1] &= 0xFFFF0000u;
                if (c0 + 1 == ri1) pa[1] &= 0x0000FFFFu;
                if (c0 + 8 == ri0) pa[2] &= 0xFFFF0000u;
                if (c0 + 9 == ri0) pa[2] &= 0x0000FFFFu;
                if (c0 + 8 == ri1) pa[3] &= 0xFFFF0000u;
                if (c0 + 9 == ri1) pa[3] &= 0x0000FFFFu;
            }
            mma_f16(lacc, pa[0], pa[1], pa[2], pa[3], ONES, ONES);
            uint32 vf[4][4];
#pragma unroll
            for (int pp = 0; pp < 4; pp++)
                ldm4(vf[pp][0], vf[pp][1], vf[pp][2], vf[pp][3],
                     vb + swz((uint32)((pp * 16 + rkl) * 128 + s * 32 + ckl)));
#pragma unroll
            for (int dt = 0; dt < 8; dt++)
                mma_f16(o[dt], pa[0], pa[1], pa[2], pa[3],
                        vf[dt >> 1][(dt & 1) * 2], vf[dt >> 1][(dt & 1) * 2 + 1]);
        }

        __syncthreads();                         // all warps done with buffer p
        if (i + 2 < SEQ / 64) {
            attn_stage_k(kb, bh, j0 + 128);
            attn_stage_v(vb, bh, j0 + 128);
        }
        cp_commit();
    }

    const int b = bh >> 4, head = bh & 15;
    const float inv0 = 1.f / lacc[0], inv1 = 1.f / lacc[2];
#pragma unroll
    for (int dt = 0; dt < 8; dt++) {
        const int ip = head * 32 + dt * 4 + tig;
#pragma unroll
        for (int slot = 0; slot < 2; slot++) {
            const float inv = slot ? inv1 : inv0;
            const int m = b * SEQ + qrow + g + slot * 8;
            g_ao[m][ip] = cvt_h2(o[dt][slot*2] * inv, o[dt][slot*2 + 1] * inv);
        }
    }
}

// ---------------- kernel 3: output projection -------------------------------
__global__ __launch_bounds__(256, 2) void out_gemm_kernel(
    const float* __restrict__ bias, float* __restrict__ out)
{
    __shared__ __align__(128) uint32 smp[3][4096];   // 48KB
    const uint32 sbase = smem_u32(smp);
    const int row0 = blockIdx.x * 128, col0 = blockIdx.y * 128;
    const uint32 *A = &g_ao[row0][0], *B = &g_wout[col0][0];
    const int iters = INNER / 32;

    float acc[2][8][4];
#pragma unroll
    for (int i = 0; i < 2; i++)
#pragma unroll
        for (int j = 0; j < 8; j++)
#pragma unroll
            for (int e = 0; e < 4; e++) acc[i][j][e] = 0.f;

    gemm_stage(sbase, 0, A, B, INNER/2, 0); cp_commit();
    gemm_stage(sbase, 1, A, B, INNER/2, 1); cp_commit();

    for (int it = 0; it < iters; it++) {
        cp_wait<1>(); __syncthreads();
        gemm_compute(sbase, it % 3, acc);
        if (it + 2 < iters)
            gemm_stage(sbase, (it + 2) % 3, A, B, INNER/2, it + 2);
        cp_commit();
    }

    const int lane = threadIdx.x & 31, warp = threadIdx.x >> 5;
    const int wm = warp & 3, wn = warp >> 2;
    const int g = lane >> 2, tig = lane & 3;
#pragma unroll
    for (int mt = 0; mt < 2; mt++) {
        const int m = row0 + wm * 32 + mt * 16 + g;
#pragma unroll
        for (int nt = 0; nt < 8; nt++) {
            const int n = col0 + wn * 64 + nt * 8 + tig * 2;
            const float b0 = bias[n], b1 = bias[n + 1];
#pragma unroll
            for (int slot = 0; slot < 2; slot++) {
                float2 r;
                r.x = acc[mt][nt][slot*2]     + b0;
                r.y = acc[mt][nt][slot*2 + 1] + b1;
                *(float2*)&out[(size_t)(m + slot * 8) * DIM + n] = r;
            }
        }
    }
}

// ---------------------------------------------------------------------------
extern "C" void kernel_launch(void* const* d_in, const int* in_sizes, int n_in,
                              void* d_out, int out_size)
{
    const float* x    = (const float*)d_in[0];
    const float* wqkv = (const float*)d_in[1];
    const float* wout = (const float*)d_in[2];
    const float* bout = (const float*)d_in[3];
    const float* temp = (const float*)d_in[4];
    float* out = (float*)d_out;

    pack_x_kernel<<<(MTOT * DIM / 2) / 256, 256>>>(x);
    pack_wT_kernel<<<dim3(DIM / 64, QKVN / 64), 256>>>(wqkv, 0);
    pack_wT_kernel<<<dim3(INNER / 64, DIM / 64), 256>>>(wout, 1);
    qkv_gemm_kernel<<<dim3(MTOT / 128, QKVN / 128), 256>>>(temp);
    vT_kernel<<<dim3(SEQ / 64, BH), 256>>>();
    attn_kernel<<<dim3(SEQ / 128, BH), 256>>>();
    out_gemm_kernel<<<dim3(MTOT / 128, DIM / 128), 256>>>(bout, out);
}